// round 4
// baseline (speedup 1.0000x reference)
#include <cuda_runtime.h>
#include <math.h>
#include <stdint.h>

// ---------------------------------------------------------------------------
// AutomaticBrightnessAndContrast  (3, H, W) float32 planar
//
//   k_init   : zero global hists + max accumulator (runs every graph replay)
//   k_pass1  : ONE read of image -> global max + histogram under scale=255
//              hypothesis. Per-thread private u8 shared histograms,
//              bank-conflict-free, ZERO atomics in the hot loop.
//   k_flag   : is_norm = (max <= 1)
//   k_histB  : fallback histogram (scale=1); uniform early-exit when is_norm.
//   k_params : cumsum -> alpha/beta (1 thread, 256 iters)
//   k_apply  : out = clip(in*alpha_eff + beta_eff, 0, hi)   (or copy)
// ---------------------------------------------------------------------------

#define NBINS 256
#define T_PER_B 256
#define HIST_BLOCKS 304               // 2/SM on 152 SMs; u8 bound: <=216 incr/thread < 255
#define HIST_SMEM (NBINS * T_PER_B)   // 64 KB of u8 counters

__device__ unsigned int d_histA[NBINS];   // scale = 255 hypothesis
__device__ unsigned int d_histB[NBINS];   // scale = 1 hypothesis
__device__ unsigned int d_maxEnc;
__device__ int   d_isNorm;
__device__ float d_alpha_eff, d_beta_eff, d_hi;
__device__ int   d_apply;

__device__ __forceinline__ unsigned int enc_f(float f) {
    unsigned int u = __float_as_uint(f);
    return (u & 0x80000000u) ? ~u : (u | 0x80000000u);
}
__device__ __forceinline__ float dec_f(unsigned int e) {
    unsigned int u = (e & 0x80000000u) ? (e & 0x7FFFFFFFu) : ~e;
    return __uint_as_float(u);
}

__global__ void k_init() {
    int i = threadIdx.x;
    if (i < NBINS) { d_histA[i] = 0u; d_histB[i] = 0u; }
    if (i == 0) d_maxEnc = 0u;
}

// bin index per reference: idx = clip(floor(g / (255/256)), 0, 255); valid g in [0,255]
__device__ __forceinline__ int bin_of(float g) {
    float q = __fdiv_rn(g, 0.99609375f);   // 255/256 exactly representable; IEEE rn div
    int b = __float2int_rd(q);
    return min(max(b, 0), NBINS - 1);
}

// gray with reference op order and separate rounding (no FMA contraction)
__device__ __forceinline__ float gray_of(float r, float g, float b) {
    float t0 = __fmul_rn(0.299f, r);
    float t1 = __fmul_rn(0.587f, g);
    float t2 = __fmul_rn(0.114f, b);
    return __fadd_rn(__fadd_rn(t0, t1), t2);
}

// bank-conflict-free private column for thread t:
// byte's 4B word index mod 32 == lane  -> distinct banks within every warp
__device__ __forceinline__ int col_of(int t) {
    int l = t & 31, w = t >> 5;
    return 4 * l + (w & 3) + ((w >> 2) << 7);
}

__device__ __forceinline__ void hupd(unsigned char* sh, int bin, int col) {
    sh[bin * T_PER_B + col] = (unsigned char)(sh[bin * T_PER_B + col] + 1);
}

template <int SCALE_IS_255>
__device__ __forceinline__ void hist_body(const float* __restrict__ img, int npix4,
                                          unsigned int* __restrict__ hist_out,
                                          bool do_max) {
    extern __shared__ unsigned char sh8[];
    for (int i = threadIdx.x; i < HIST_SMEM / 4; i += blockDim.x)
        ((unsigned int*)sh8)[i] = 0u;
    __syncthreads();

    const float4* __restrict__ R = (const float4*)img;
    const float4* __restrict__ G = R + npix4;
    const float4* __restrict__ B = G + npix4;

    const int col = col_of(threadIdx.x);
    const int stride = gridDim.x * blockDim.x;
    int i = blockIdx.x * blockDim.x + threadIdx.x;

    float lmax = -3.402823466e38f;

    // 2x-unrolled grid-stride main loop (12 LDG.128 in flight per iter)
    for (; i + stride < npix4; i += 2 * stride) {
        float4 r0 = R[i], g0 = G[i], b0 = B[i];
        float4 r1 = R[i + stride], g1 = G[i + stride], b1 = B[i + stride];
        if (do_max) {
            lmax = fmaxf(lmax, fmaxf(fmaxf(r0.x, r0.y), fmaxf(r0.z, r0.w)));
            lmax = fmaxf(lmax, fmaxf(fmaxf(g0.x, g0.y), fmaxf(g0.z, g0.w)));
            lmax = fmaxf(lmax, fmaxf(fmaxf(b0.x, b0.y), fmaxf(b0.z, b0.w)));
            lmax = fmaxf(lmax, fmaxf(fmaxf(r1.x, r1.y), fmaxf(r1.z, r1.w)));
            lmax = fmaxf(lmax, fmaxf(fmaxf(g1.x, g1.y), fmaxf(g1.z, g1.w)));
            lmax = fmaxf(lmax, fmaxf(fmaxf(b1.x, b1.y), fmaxf(b1.z, b1.w)));
        }
        #define PX(rr, gg, bb) do {                                            \
            float ra = rr, ga = gg, ba = bb;                                   \
            if (SCALE_IS_255) {                                                \
                ra = __fmul_rn(ra, 255.0f);                                    \
                ga = __fmul_rn(ga, 255.0f);                                    \
                ba = __fmul_rn(ba, 255.0f);                                    \
            }                                                                  \
            float gy = gray_of(ra, ga, ba);                                    \
            if (gy >= 0.0f && gy <= 255.0f) hupd(sh8, bin_of(gy), col);        \
        } while (0)
        PX(r0.x, g0.x, b0.x); PX(r0.y, g0.y, b0.y);
        PX(r0.z, g0.z, b0.z); PX(r0.w, g0.w, b0.w);
        PX(r1.x, g1.x, b1.x); PX(r1.y, g1.y, b1.y);
        PX(r1.z, g1.z, b1.z); PX(r1.w, g1.w, b1.w);
    }
    if (i < npix4) {
        float4 r0 = R[i], g0 = G[i], b0 = B[i];
        if (do_max) {
            lmax = fmaxf(lmax, fmaxf(fmaxf(r0.x, r0.y), fmaxf(r0.z, r0.w)));
            lmax = fmaxf(lmax, fmaxf(fmaxf(g0.x, g0.y), fmaxf(g0.z, g0.w)));
            lmax = fmaxf(lmax, fmaxf(fmaxf(b0.x, b0.y), fmaxf(b0.z, b0.w)));
        }
        PX(r0.x, g0.x, b0.x); PX(r0.y, g0.y, b0.y);
        PX(r0.z, g0.z, b0.z); PX(r0.w, g0.w, b0.w);
        #undef PX
    }

    if (do_max) {
        __shared__ float smax[8];
        int lane = threadIdx.x & 31, warp = threadIdx.x >> 5;
        #pragma unroll
        for (int o = 16; o; o >>= 1)
            lmax = fmaxf(lmax, __shfl_xor_sync(0xFFFFFFFFu, lmax, o));
        if (lane == 0) smax[warp] = lmax;
        __syncthreads();
        if (threadIdx.x < 8) {
            float v = smax[threadIdx.x];
            #pragma unroll
            for (int o = 4; o; o >>= 1)
                v = fmaxf(v, __shfl_xor_sync(0xFFu, v, o));
            if (threadIdx.x == 0) atomicMax(&d_maxEnc, enc_f(v));
        }
    }
    __syncthreads();

    // flush: thread t sums bin t's 256 u8 columns via dp4a (skewed uint4 loads)
    {
        int t = threadIdx.x;
        const uint4* row = (const uint4*)(sh8 + t * T_PER_B);
        unsigned int s = 0;
        #pragma unroll
        for (int j = 0; j < 16; j++) {
            int k = (j + (t & 15)) & 15;
            uint4 v = row[k];
            s = __dp4a(v.x, 0x01010101u, s);
            s = __dp4a(v.y, 0x01010101u, s);
            s = __dp4a(v.z, 0x01010101u, s);
            s = __dp4a(v.w, 0x01010101u, s);
        }
        atomicAdd(&hist_out[t], s);
    }
}

__global__ void __launch_bounds__(T_PER_B, 2)
k_pass1(const float* __restrict__ img, int npix4) {
    hist_body<1>(img, npix4, d_histA, true);
}

__global__ void k_flag() {
    if (threadIdx.x == 0)
        d_isNorm = (dec_f(d_maxEnc) <= 1.0f) ? 1 : 0;
}

__global__ void __launch_bounds__(T_PER_B, 2)
k_histB(const float* __restrict__ img, int npix4) {
    if (d_isNorm) return;   // uniform early-exit: normalized input never needs this
    hist_body<0>(img, npix4, d_histB, false);
}

__global__ void k_params() {
    if (threadIdx.x != 0 || blockIdx.x != 0) return;

    bool is_norm = (d_isNorm != 0);
    const unsigned int* h = is_norm ? d_histA : d_histB;

    long long tot = 0;
    for (int i = 0; i < NBINS; i++) tot += (long long)h[i];
    float maximum = (float)tot;                       // exact (counts <= 2^24)
    float clip_value = __fmul_rn(__fdiv_rn(maximum, 100.0f), 0.5f);
    float thresh_hi = __fsub_rn(maximum, clip_value);

    long long acc = 0;
    int min_gray = 0, cnt_hi = 0;
    for (int i = 0; i < NBINS; i++) {
        acc += (long long)h[i];
        float accf = (float)acc;                      // exact
        if (accf < clip_value) min_gray++;
        if (accf < thresh_hi)  cnt_hi++;
    }
    int max_gray = cnt_hi - 1;

    int sp = max_gray - min_gray; if (sp < 1) sp = 1;
    float alpha = __fdiv_rn(255.0f, (float)sp);
    float beta  = __fmul_rn(-(float)min_gray, alpha);
    float scl   = is_norm ? 255.0f : 1.0f;

    d_alpha_eff = __fdiv_rn(alpha, scl);
    d_beta_eff  = __fdiv_rn(beta,  scl);
    d_hi        = is_norm ? 1.0f : 255.0f;
    d_apply     = (max_gray > min_gray) ? 1 : 0;
}

__global__ void __launch_bounds__(256)
k_apply(const float* __restrict__ in, float* __restrict__ out, int n4) {
    const float a  = d_alpha_eff;
    const float b  = d_beta_eff;
    const float hi = d_hi;
    const int   ap = d_apply;

    const float4* __restrict__ I = (const float4*)in;
    float4*       __restrict__ O = (float4*)out;
    const int stride = gridDim.x * blockDim.x;
    int i = blockIdx.x * blockDim.x + threadIdx.x;

    if (ap) {
        for (; i + 3 * stride < n4; i += 4 * stride) {
            float4 v0 = I[i], v1 = I[i + stride], v2 = I[i + 2 * stride], v3 = I[i + 3 * stride];
            #define ADJ(v) do {                                                \
                v.x = fminf(fmaxf(fmaf(v.x, a, b), 0.0f), hi);                 \
                v.y = fminf(fmaxf(fmaf(v.y, a, b), 0.0f), hi);                 \
                v.z = fminf(fmaxf(fmaf(v.z, a, b), 0.0f), hi);                 \
                v.w = fminf(fmaxf(fmaf(v.w, a, b), 0.0f), hi);                 \
            } while (0)
            ADJ(v0); ADJ(v1); ADJ(v2); ADJ(v3);
            O[i] = v0; O[i + stride] = v1; O[i + 2 * stride] = v2; O[i + 3 * stride] = v3;
        }
        for (; i < n4; i += stride) {
            float4 v = I[i];
            ADJ(v);
            #undef ADJ
            O[i] = v;
        }
    } else {
        for (; i < n4; i += stride) O[i] = I[i];
    }
}

extern "C" void kernel_launch(void* const* d_in, const int* in_sizes, int n_in,
                              void* d_out, int out_size) {
    const float* img = (const float*)d_in[0];
    float* out = (float*)d_out;
    int n = in_sizes[0];         // 3*H*W
    int npix4 = (n / 3) / 4;
    int n4 = n / 4;

    // opt-in to 64KB dynamic smem (eager host API, legal under capture, no alloc)
    cudaFuncSetAttribute(k_pass1, cudaFuncAttributeMaxDynamicSharedMemorySize, HIST_SMEM);
    cudaFuncSetAttribute(k_histB, cudaFuncAttributeMaxDynamicSharedMemorySize, HIST_SMEM);

    k_init<<<1, 256>>>();
    k_pass1<<<HIST_BLOCKS, T_PER_B, HIST_SMEM>>>(img, npix4);
    k_flag<<<1, 32>>>();
    k_histB<<<HIST_BLOCKS, T_PER_B, HIST_SMEM>>>(img, npix4);
    k_params<<<1, 32>>>();
    k_apply<<<6144, 256>>>(img, out, n4);
}

// round 13
// speedup vs baseline: 1.0124x; 1.0124x over previous
#include <cuda_runtime.h>
#include <math.h>
#include <stdint.h>

// ---------------------------------------------------------------------------
// AutomaticBrightnessAndContrast  (3, H, W) float32 planar — 4-launch version
//
//   k_pass1  : ONE read -> global max (atomicMax) + histogram (scale=255
//              hypothesis) in per-thread private u8 smem counters,
//              bank-conflict-free, zero atomics in hot loop; per-block
//              partial sums to global (plain stores, no init needed).
//   k_histB  : fallback histogram (scale=1); reads d_maxEnc, uniform
//              early-exit when is_norm.
//   k_params : sum partials (256 thr), cumsum -> alpha/beta; resets d_maxEnc.
//   k_apply  : out = clip(in*alpha_eff + beta_eff, 0, hi)  via __ldcs/__stwt
// ---------------------------------------------------------------------------

#define NBINS 256
#define T_PER_B 256
#define HIST_BLOCKS 456               // 3/SM on 152 SMs; u8 bound: <=144 incr/thread < 255
#define HIST_SMEM (NBINS * T_PER_B)   // 64 KB of u8 counters

__device__ unsigned int d_partA[HIST_BLOCKS * NBINS];   // scale=255 hypothesis partials
__device__ unsigned int d_partB[HIST_BLOCKS * NBINS];   // scale=1 hypothesis partials
__device__ unsigned int d_maxEnc = 0u;                  // order-encoded max; params resets
__device__ float d_alpha_eff, d_beta_eff, d_hi;
__device__ int   d_apply;

__device__ __forceinline__ unsigned int enc_f(float f) {
    unsigned int u = __float_as_uint(f);
    return (u & 0x80000000u) ? ~u : (u | 0x80000000u);
}
__device__ __forceinline__ float dec_f(unsigned int e) {
    unsigned int u = (e & 0x80000000u) ? (e & 0x7FFFFFFFu) : ~e;
    return __uint_as_float(u);
}

// bin index per reference: idx = clip(floor(g / (255/256)), 0, 255); valid g in [0,255]
__device__ __forceinline__ int bin_of(float g) {
    float q = __fdiv_rn(g, 0.99609375f);   // 255/256 exact; IEEE rn division
    int b = __float2int_rd(q);
    return min(max(b, 0), NBINS - 1);
}

// gray with reference op order, separate rounding (no FMA contraction)
__device__ __forceinline__ float gray_of(float r, float g, float b) {
    float t0 = __fmul_rn(0.299f, r);
    float t1 = __fmul_rn(0.587f, g);
    float t2 = __fmul_rn(0.114f, b);
    return __fadd_rn(__fadd_rn(t0, t1), t2);
}

// bank-conflict-free private column for thread t:
// byte's 4B word index mod 32 == lane -> distinct banks within every warp
__device__ __forceinline__ int col_of(int t) {
    int l = t & 31, w = t >> 5;
    return 4 * l + (w & 3) + ((w >> 2) << 7);
}

__device__ __forceinline__ void hupd(unsigned char* sh, int bin, int col) {
    sh[bin * T_PER_B + col] = (unsigned char)(sh[bin * T_PER_B + col] + 1);
}

template <int SCALE_IS_255>
__device__ __forceinline__ void hist_body(const float* __restrict__ img, int npix4,
                                          unsigned int* __restrict__ part_out,
                                          bool do_max) {
    extern __shared__ unsigned char sh8[];
    for (int i = threadIdx.x; i < HIST_SMEM / 4; i += blockDim.x)
        ((unsigned int*)sh8)[i] = 0u;
    __syncthreads();

    const float4* __restrict__ R = (const float4*)img;
    const float4* __restrict__ G = R + npix4;
    const float4* __restrict__ B = G + npix4;

    const int col = col_of(threadIdx.x);
    const int stride = gridDim.x * blockDim.x;
    int i = blockIdx.x * blockDim.x + threadIdx.x;

    float lmax = -3.402823466e38f;

    // 2x-unrolled grid-stride main loop (12 LDG.128 in flight per iter)
    for (; i + stride < npix4; i += 2 * stride) {
        float4 r0 = R[i], g0 = G[i], b0 = B[i];
        float4 r1 = R[i + stride], g1 = G[i + stride], b1 = B[i + stride];
        if (do_max) {
            lmax = fmaxf(lmax, fmaxf(fmaxf(r0.x, r0.y), fmaxf(r0.z, r0.w)));
            lmax = fmaxf(lmax, fmaxf(fmaxf(g0.x, g0.y), fmaxf(g0.z, g0.w)));
            lmax = fmaxf(lmax, fmaxf(fmaxf(b0.x, b0.y), fmaxf(b0.z, b0.w)));
            lmax = fmaxf(lmax, fmaxf(fmaxf(r1.x, r1.y), fmaxf(r1.z, r1.w)));
            lmax = fmaxf(lmax, fmaxf(fmaxf(g1.x, g1.y), fmaxf(g1.z, g1.w)));
            lmax = fmaxf(lmax, fmaxf(fmaxf(b1.x, b1.y), fmaxf(b1.z, b1.w)));
        }
        #define PX(rr, gg, bb) do {                                            \
            float ra = rr, ga = gg, ba = bb;                                   \
            if (SCALE_IS_255) {                                                \
                ra = __fmul_rn(ra, 255.0f);                                    \
                ga = __fmul_rn(ga, 255.0f);                                    \
                ba = __fmul_rn(ba, 255.0f);                                    \
            }                                                                  \
            float gy = gray_of(ra, ga, ba);                                    \
            if (gy >= 0.0f && gy <= 255.0f) hupd(sh8, bin_of(gy), col);        \
        } while (0)
        PX(r0.x, g0.x, b0.x); PX(r0.y, g0.y, b0.y);
        PX(r0.z, g0.z, b0.z); PX(r0.w, g0.w, b0.w);
        PX(r1.x, g1.x, b1.x); PX(r1.y, g1.y, b1.y);
        PX(r1.z, g1.z, b1.z); PX(r1.w, g1.w, b1.w);
    }
    if (i < npix4) {
        float4 r0 = R[i], g0 = G[i], b0 = B[i];
        if (do_max) {
            lmax = fmaxf(lmax, fmaxf(fmaxf(r0.x, r0.y), fmaxf(r0.z, r0.w)));
            lmax = fmaxf(lmax, fmaxf(fmaxf(g0.x, g0.y), fmaxf(g0.z, g0.w)));
            lmax = fmaxf(lmax, fmaxf(fmaxf(b0.x, b0.y), fmaxf(b0.z, b0.w)));
        }
        PX(r0.x, g0.x, b0.x); PX(r0.y, g0.y, b0.y);
        PX(r0.z, g0.z, b0.z); PX(r0.w, g0.w, b0.w);
        #undef PX
    }

    if (do_max) {
        __shared__ float smax[8];
        int lane = threadIdx.x & 31, warp = threadIdx.x >> 5;
        #pragma unroll
        for (int o = 16; o; o >>= 1)
            lmax = fmaxf(lmax, __shfl_xor_sync(0xFFFFFFFFu, lmax, o));
        if (lane == 0) smax[warp] = lmax;
        __syncthreads();
        if (threadIdx.x < 8) {
            float v = smax[threadIdx.x];
            #pragma unroll
            for (int o = 4; o; o >>= 1)
                v = fmaxf(v, __shfl_xor_sync(0xFFu, v, o));
            if (threadIdx.x == 0) atomicMax(&d_maxEnc, enc_f(v));
        }
    }
    __syncthreads();

    // flush: thread t sums bin t's 256 u8 columns via dp4a (skewed uint4 loads),
    // writes this block's partial -> no atomics, no zero-init required.
    {
        int t = threadIdx.x;
        const uint4* row = (const uint4*)(sh8 + t * T_PER_B);
        unsigned int s = 0;
        #pragma unroll
        for (int j = 0; j < 16; j++) {
            int k = (j + (t & 15)) & 15;
            uint4 v = row[k];
            s = __dp4a(v.x, 0x01010101u, s);
            s = __dp4a(v.y, 0x01010101u, s);
            s = __dp4a(v.z, 0x01010101u, s);
            s = __dp4a(v.w, 0x01010101u, s);
        }
        part_out[blockIdx.x * NBINS + t] = s;
    }
}

__global__ void __launch_bounds__(T_PER_B, 3)
k_pass1(const float* __restrict__ img, int npix4) {
    hist_body<1>(img, npix4, d_partA, true);
}

__global__ void __launch_bounds__(T_PER_B, 3)
k_histB(const float* __restrict__ img, int npix4) {
    if (dec_f(d_maxEnc) <= 1.0f) return;   // uniform early-exit when normalized
    hist_body<0>(img, npix4, d_partB, false);
}

__global__ void k_params() {
    __shared__ unsigned int sh[NBINS];
    bool is_norm = (dec_f(d_maxEnc) <= 1.0f);
    const unsigned int* __restrict__ part = is_norm ? d_partA : d_partB;

    int t = threadIdx.x;
    unsigned int s = 0;
    #pragma unroll 8
    for (int b = 0; b < HIST_BLOCKS; b++)
        s += part[b * NBINS + t];
    sh[t] = s;
    __syncthreads();

    if (t == 0) {
        long long tot = 0;
        for (int i = 0; i < NBINS; i++) tot += (long long)sh[i];
        float maximum = (float)tot;                       // exact (<= 2^24)
        float clip_value = __fmul_rn(__fdiv_rn(maximum, 100.0f), 0.5f);
        float thresh_hi = __fsub_rn(maximum, clip_value);

        long long acc = 0;
        int min_gray = 0, cnt_hi = 0;
        for (int i = 0; i < NBINS; i++) {
            acc += (long long)sh[i];
            float accf = (float)acc;                      // exact
            if (accf < clip_value) min_gray++;
            if (accf < thresh_hi)  cnt_hi++;
        }
        int max_gray = cnt_hi - 1;

        int sp = max_gray - min_gray; if (sp < 1) sp = 1;
        float alpha = __fdiv_rn(255.0f, (float)sp);
        float beta  = __fmul_rn(-(float)min_gray, alpha);
        float scl   = is_norm ? 255.0f : 1.0f;

        d_alpha_eff = __fdiv_rn(alpha, scl);
        d_beta_eff  = __fdiv_rn(beta,  scl);
        d_hi        = is_norm ? 1.0f : 255.0f;
        d_apply     = (max_gray > min_gray) ? 1 : 0;

        d_maxEnc = 0u;   // self-reset for next graph replay
    }
}

__global__ void __launch_bounds__(256)
k_apply(const float* __restrict__ in, float* __restrict__ out, int n4) {
    const float a  = d_alpha_eff;
    const float b  = d_beta_eff;
    const float hi = d_hi;
    const int   ap = d_apply;

    const float4* __restrict__ I = (const float4*)in;
    float4*       __restrict__ O = (float4*)out;
    const int stride = gridDim.x * blockDim.x;
    int i = blockIdx.x * blockDim.x + threadIdx.x;

    if (ap) {
        for (; i + 3 * stride < n4; i += 4 * stride) {
            float4 v0 = __ldcs(&I[i]);
            float4 v1 = __ldcs(&I[i + stride]);
            float4 v2 = __ldcs(&I[i + 2 * stride]);
            float4 v3 = __ldcs(&I[i + 3 * stride]);
            #define ADJ(v) do {                                                \
                v.x = fminf(fmaxf(fmaf(v.x, a, b), 0.0f), hi);                 \
                v.y = fminf(fmaxf(fmaf(v.y, a, b), 0.0f), hi);                 \
                v.z = fminf(fmaxf(fmaf(v.z, a, b), 0.0f), hi);                 \
                v.w = fminf(fmaxf(fmaf(v.w, a, b), 0.0f), hi);                 \
            } while (0)
            ADJ(v0); ADJ(v1); ADJ(v2); ADJ(v3);
            __stwt(&O[i], v0);
            __stwt(&O[i + stride], v1);
            __stwt(&O[i + 2 * stride], v2);
            __stwt(&O[i + 3 * stride], v3);
        }
        for (; i < n4; i += stride) {
            float4 v = __ldcs(&I[i]);
            ADJ(v);
            #undef ADJ
            __stwt(&O[i], v);
        }
    } else {
        for (; i < n4; i += stride) {
            __stwt(&O[i], __ldcs(&I[i]));
        }
    }
}

extern "C" void kernel_launch(void* const* d_in, const int* in_sizes, int n_in,
                              void* d_out, int out_size) {
    const float* img = (const float*)d_in[0];
    float* out = (float*)d_out;
    int n = in_sizes[0];         // 3*H*W
    int npix4 = (n / 3) / 4;
    int n4 = n / 4;

    // opt-in to 64KB dynamic smem (eager host API, capture-legal, no allocation)
    cudaFuncSetAttribute(k_pass1, cudaFuncAttributeMaxDynamicSharedMemorySize, HIST_SMEM);
    cudaFuncSetAttribute(k_histB, cudaFuncAttributeMaxDynamicSharedMemorySize, HIST_SMEM);

    k_pass1<<<HIST_BLOCKS, T_PER_B, HIST_SMEM>>>(img, npix4);
    k_histB<<<HIST_BLOCKS, T_PER_B, HIST_SMEM>>>(img, npix4);
    k_params<<<1, 256>>>();
    k_apply<<<4864, 256>>>(img, out, n4);
}

// round 14
// speedup vs baseline: 1.0156x; 1.0032x over previous
#include <cuda_runtime.h>
#include <math.h>
#include <stdint.h>

// ---------------------------------------------------------------------------
// AutomaticBrightnessAndContrast  (3, H, W) float32 planar — 4-launch version
//
//   k_pass1  : ONE read -> global max + histogram (scale=255 hypothesis) in
//              per-thread private u8 smem counters; branch-free exact binning
//              (no FDIV/BSSY in the hot loop); per-block partial-sum flush.
//   k_histB  : fallback histogram (scale=1); uniform early-exit when is_norm.
//   k_params : sum partials, cumsum -> alpha/beta; resets d_maxEnc.
//   k_apply  : out = clip(in*alpha_eff + beta_eff, 0, hi)  via __ldcs/__stwt
// ---------------------------------------------------------------------------

#define NBINS 256
#define T_PER_B 256
#define HIST_BLOCKS 456               // 3/SM on 152 SMs; u8 bound: <=144 incr/thread < 255
#define HIST_SMEM (NBINS * T_PER_B)   // 64 KB of u8 counters

__device__ unsigned int d_partA[HIST_BLOCKS * NBINS];   // scale=255 hypothesis partials
__device__ unsigned int d_partB[HIST_BLOCKS * NBINS];   // scale=1 hypothesis partials
__device__ unsigned int d_maxEnc = 0u;                  // order-encoded max; params resets
__device__ float d_alpha_eff, d_beta_eff, d_hi;
__device__ int   d_apply;

__device__ __forceinline__ unsigned int enc_f(float f) {
    unsigned int u = __float_as_uint(f);
    return (u & 0x80000000u) ? ~u : (u | 0x80000000u);
}
__device__ __forceinline__ float dec_f(unsigned int e) {
    unsigned int u = (e & 0x80000000u) ? (e & 0x7FFFFFFFu) : ~e;
    return __uint_as_float(u);
}

// Branch-free exact binning. Reference: idx = clip(floor(fdiv_rn(g, 255/256)),0,255).
// Boundaries b(j) = j*(255/256) are EXACT floats (j*255 < 2^24; /256 = exp shift).
// Proof sketch: for any float g, the real quotient g/c is >= 1.0039 ulp away from
// the nearest integer unless g == b(k) exactly, so fdiv_rn never rounds across an
// integer and floor(fdiv_rn(g,c)) == floor_real(g/c). We compute floor_real via
// reciprocal-multiply estimate + two exact-comparison corrections.
__device__ __forceinline__ int bin_of(float g) {
    float q = __fmul_rn(g, 1.0039215686274509804f);     // RN(256/255)
    int k = __float2int_rd(q);                          // within +-1 of true bin
    float bk = __fmul_rn(__int2float_rn(k), 0.99609375f);      // exact b(k)
    if (g < bk) k -= 1;
    float bk1 = __fmul_rn(__int2float_rn(k + 1), 0.99609375f); // exact b(k+1)
    if (g >= bk1) k += 1;
    return min(max(k, 0), NBINS - 1);
}

// gray with reference op order, separate rounding (no FMA contraction)
__device__ __forceinline__ float gray_of(float r, float g, float b) {
    float t0 = __fmul_rn(0.299f, r);
    float t1 = __fmul_rn(0.587f, g);
    float t2 = __fmul_rn(0.114f, b);
    return __fadd_rn(__fadd_rn(t0, t1), t2);
}

// bank-conflict-free private column for thread t:
// byte's 4B word index mod 32 == lane -> distinct banks within every warp
__device__ __forceinline__ int col_of(int t) {
    int l = t & 31, w = t >> 5;
    return 4 * l + (w & 3) + ((w >> 2) << 7);
}

__device__ __forceinline__ void hupd(unsigned char* sh, int bin, int col) {
    sh[bin * T_PER_B + col] = (unsigned char)(sh[bin * T_PER_B + col] + 1);
}

template <int SCALE_IS_255>
__device__ __forceinline__ void hist_body(const float* __restrict__ img, int npix4,
                                          unsigned int* __restrict__ part_out,
                                          bool do_max) {
    extern __shared__ unsigned char sh8[];
    for (int i = threadIdx.x; i < HIST_SMEM / 4; i += blockDim.x)
        ((unsigned int*)sh8)[i] = 0u;
    __syncthreads();

    const float4* __restrict__ R = (const float4*)img;
    const float4* __restrict__ G = R + npix4;
    const float4* __restrict__ B = G + npix4;

    const int col = col_of(threadIdx.x);
    const int stride = gridDim.x * blockDim.x;
    int i = blockIdx.x * blockDim.x + threadIdx.x;

    float lmax = -3.402823466e38f;

    // 2x-unrolled grid-stride main loop (12 LDG.128 in flight per iter)
    for (; i + stride < npix4; i += 2 * stride) {
        float4 r0 = R[i], g0 = G[i], b0 = B[i];
        float4 r1 = R[i + stride], g1 = G[i + stride], b1 = B[i + stride];
        if (do_max) {
            lmax = fmaxf(lmax, fmaxf(fmaxf(r0.x, r0.y), fmaxf(r0.z, r0.w)));
            lmax = fmaxf(lmax, fmaxf(fmaxf(g0.x, g0.y), fmaxf(g0.z, g0.w)));
            lmax = fmaxf(lmax, fmaxf(fmaxf(b0.x, b0.y), fmaxf(b0.z, b0.w)));
            lmax = fmaxf(lmax, fmaxf(fmaxf(r1.x, r1.y), fmaxf(r1.z, r1.w)));
            lmax = fmaxf(lmax, fmaxf(fmaxf(g1.x, g1.y), fmaxf(g1.z, g1.w)));
            lmax = fmaxf(lmax, fmaxf(fmaxf(b1.x, b1.y), fmaxf(b1.z, b1.w)));
        }
        #define PX(rr, gg, bb) do {                                            \
            float ra = rr, ga = gg, ba = bb;                                   \
            if (SCALE_IS_255) {                                                \
                ra = __fmul_rn(ra, 255.0f);                                    \
                ga = __fmul_rn(ga, 255.0f);                                    \
                ba = __fmul_rn(ba, 255.0f);                                    \
            }                                                                  \
            float gy = gray_of(ra, ga, ba);                                    \
            if (gy >= 0.0f && gy <= 255.0f) hupd(sh8, bin_of(gy), col);        \
        } while (0)
        PX(r0.x, g0.x, b0.x); PX(r0.y, g0.y, b0.y);
        PX(r0.z, g0.z, b0.z); PX(r0.w, g0.w, b0.w);
        PX(r1.x, g1.x, b1.x); PX(r1.y, g1.y, b1.y);
        PX(r1.z, g1.z, b1.z); PX(r1.w, g1.w, b1.w);
    }
    if (i < npix4) {
        float4 r0 = R[i], g0 = G[i], b0 = B[i];
        if (do_max) {
            lmax = fmaxf(lmax, fmaxf(fmaxf(r0.x, r0.y), fmaxf(r0.z, r0.w)));
            lmax = fmaxf(lmax, fmaxf(fmaxf(g0.x, g0.y), fmaxf(g0.z, g0.w)));
            lmax = fmaxf(lmax, fmaxf(fmaxf(b0.x, b0.y), fmaxf(b0.z, b0.w)));
        }
        PX(r0.x, g0.x, b0.x); PX(r0.y, g0.y, b0.y);
        PX(r0.z, g0.z, b0.z); PX(r0.w, g0.w, b0.w);
        #undef PX
    }

    if (do_max) {
        __shared__ float smax[8];
        int lane = threadIdx.x & 31, warp = threadIdx.x >> 5;
        #pragma unroll
        for (int o = 16; o; o >>= 1)
            lmax = fmaxf(lmax, __shfl_xor_sync(0xFFFFFFFFu, lmax, o));
        if (lane == 0) smax[warp] = lmax;
        __syncthreads();
        if (threadIdx.x < 8) {
            float v = smax[threadIdx.x];
            #pragma unroll
            for (int o = 4; o; o >>= 1)
                v = fmaxf(v, __shfl_xor_sync(0xFFu, v, o));
            if (threadIdx.x == 0) atomicMax(&d_maxEnc, enc_f(v));
        }
    }
    __syncthreads();

    // flush: thread t sums bin t's 256 u8 columns via dp4a (skewed uint4 loads),
    // writes this block's partial -> no atomics, no zero-init required.
    {
        int t = threadIdx.x;
        const uint4* row = (const uint4*)(sh8 + t * T_PER_B);
        unsigned int s = 0;
        #pragma unroll
        for (int j = 0; j < 16; j++) {
            int k = (j + (t & 15)) & 15;
            uint4 v = row[k];
            s = __dp4a(v.x, 0x01010101u, s);
            s = __dp4a(v.y, 0x01010101u, s);
            s = __dp4a(v.z, 0x01010101u, s);
            s = __dp4a(v.w, 0x01010101u, s);
        }
        part_out[blockIdx.x * NBINS + t] = s;
    }
}

__global__ void __launch_bounds__(T_PER_B, 3)
k_pass1(const float* __restrict__ img, int npix4) {
    hist_body<1>(img, npix4, d_partA, true);
}

__global__ void __launch_bounds__(T_PER_B, 3)
k_histB(const float* __restrict__ img, int npix4) {
    if (dec_f(d_maxEnc) <= 1.0f) return;   // uniform early-exit when normalized
    hist_body<0>(img, npix4, d_partB, false);
}

__global__ void k_params() {
    __shared__ unsigned int sh[NBINS];
    bool is_norm = (dec_f(d_maxEnc) <= 1.0f);
    const unsigned int* __restrict__ part = is_norm ? d_partA : d_partB;

    int t = threadIdx.x;
    unsigned int s = 0;
    #pragma unroll 8
    for (int b = 0; b < HIST_BLOCKS; b++)
        s += part[b * NBINS + t];
    sh[t] = s;
    __syncthreads();

    if (t == 0) {
        long long tot = 0;
        for (int i = 0; i < NBINS; i++) tot += (long long)sh[i];
        float maximum = (float)tot;                       // exact (<= 2^24)
        float clip_value = __fmul_rn(__fdiv_rn(maximum, 100.0f), 0.5f);
        float thresh_hi = __fsub_rn(maximum, clip_value);

        long long acc = 0;
        int min_gray = 0, cnt_hi = 0;
        for (int i = 0; i < NBINS; i++) {
            acc += (long long)sh[i];
            float accf = (float)acc;                      // exact
            if (accf < clip_value) min_gray++;
            if (accf < thresh_hi)  cnt_hi++;
        }
        int max_gray = cnt_hi - 1;

        int sp = max_gray - min_gray; if (sp < 1) sp = 1;
        float alpha = __fdiv_rn(255.0f, (float)sp);
        float beta  = __fmul_rn(-(float)min_gray, alpha);
        float scl   = is_norm ? 255.0f : 1.0f;

        d_alpha_eff = __fdiv_rn(alpha, scl);
        d_beta_eff  = __fdiv_rn(beta,  scl);
        d_hi        = is_norm ? 1.0f : 255.0f;
        d_apply     = (max_gray > min_gray) ? 1 : 0;

        d_maxEnc = 0u;   // self-reset for next graph replay
    }
}

__global__ void __launch_bounds__(256)
k_apply(const float* __restrict__ in, float* __restrict__ out, int n4) {
    const float a  = d_alpha_eff;
    const float b  = d_beta_eff;
    const float hi = d_hi;
    const int   ap = d_apply;

    const float4* __restrict__ I = (const float4*)in;
    float4*       __restrict__ O = (float4*)out;
    const int stride = gridDim.x * blockDim.x;
    int i = blockIdx.x * blockDim.x + threadIdx.x;

    if (ap) {
        for (; i + 3 * stride < n4; i += 4 * stride) {
            float4 v0 = __ldcs(&I[i]);
            float4 v1 = __ldcs(&I[i + stride]);
            float4 v2 = __ldcs(&I[i + 2 * stride]);
            float4 v3 = __ldcs(&I[i + 3 * stride]);
            #define ADJ(v) do {                                                \
                v.x = fminf(fmaxf(fmaf(v.x, a, b), 0.0f), hi);                 \
                v.y = fminf(fmaxf(fmaf(v.y, a, b), 0.0f), hi);                 \
                v.z = fminf(fmaxf(fmaf(v.z, a, b), 0.0f), hi);                 \
                v.w = fminf(fmaxf(fmaf(v.w, a, b), 0.0f), hi);                 \
            } while (0)
            ADJ(v0); ADJ(v1); ADJ(v2); ADJ(v3);
            __stwt(&O[i], v0);
            __stwt(&O[i + stride], v1);
            __stwt(&O[i + 2 * stride], v2);
            __stwt(&O[i + 3 * stride], v3);
        }
        for (; i < n4; i += stride) {
            float4 v = __ldcs(&I[i]);
            ADJ(v);
            #undef ADJ
            __stwt(&O[i], v);
        }
    } else {
        for (; i < n4; i += stride) {
            __stwt(&O[i], __ldcs(&I[i]));
        }
    }
}

extern "C" void kernel_launch(void* const* d_in, const int* in_sizes, int n_in,
                              void* d_out, int out_size) {
    const float* img = (const float*)d_in[0];
    float* out = (float*)d_out;
    int n = in_sizes[0];         // 3*H*W
    int npix4 = (n / 3) / 4;
    int n4 = n / 4;

    // opt-in to 64KB dynamic smem (eager host API, capture-legal, no allocation)
    cudaFuncSetAttribute(k_pass1, cudaFuncAttributeMaxDynamicSharedMemorySize, HIST_SMEM);
    cudaFuncSetAttribute(k_histB, cudaFuncAttributeMaxDynamicSharedMemorySize, HIST_SMEM);

    k_pass1<<<HIST_BLOCKS, T_PER_B, HIST_SMEM>>>(img, npix4);
    k_histB<<<HIST_BLOCKS, T_PER_B, HIST_SMEM>>>(img, npix4);
    k_params<<<1, 256>>>();
    k_apply<<<4864, 256>>>(img, out, n4);
}